// round 14
// baseline (speedup 1.0000x reference)
#include <cuda_runtime.h>
#include <cuda_bf16.h>
#include <cstdint>

#define BB   64
#define TT   128
#define INF  512
#define XX   2048
#define OUTF 256
#define NBLK 128
#define NTHR 512
#define KC   16
#define KSL  16
#define BBXX (BB * XX)

typedef unsigned long long ull;
typedef __nv_bfloat16 bf16;

// ---------------- persistent device scratch ----------------
__device__ __align__(16) float g_part[KSL * BBXX];            // 8MB split-K partials
__device__ __align__(16) float g_h4all[TT * BBXX];            // fp32 for postpass
__device__ __align__(16) bf16  g_h0H[TT * BBXX], g_h0L[TT * BBXX];
__device__ __align__(16) bf16  g_h4H[TT * BBXX], g_h4L[TT * BBXX];
__device__ __align__(16) bf16  g_h1H[BBXX], g_h1L[BBXX];
__device__ __align__(16) bf16  g_h2H[2][BBXX], g_h2L[2][BBXX];
__device__ __align__(16) bf16  g_h3H[BBXX], g_h3L[BBXX];
__device__ __align__(16) bf16  g_WhH[4ull * XX * 2 * XX];     // 64MB hi
__device__ __align__(16) bf16  g_WhL[4ull * XX * 2 * XX];     // 64MB lo
__device__ __align__(16) bf16  g_WiH[(size_t)XX * INF], g_WiL[(size_t)XX * INF];
__device__ __align__(16) bf16  g_xH[(size_t)BB * TT * INF], g_xL[(size_t)BB * TT * INF];
__device__ float g_liss[2][BB];
__device__ float g_bpss[2][BB];
__device__ unsigned g_bar_count;
__device__ volatile unsigned g_bar_gen;

// smem: 4 bufs x 48K {Ahi 8K|Alo 8K|Bhi 16K|Blo 16K}; wg0 owns bufs 0,1; wg1 bufs 2,3.
// postpass overlays As2/Wss; sred at 196608.
#define TILE_BUF 49152
#define A_HI 0
#define A_LO 8192
#define B_HI 16384
#define B_LO 32768
#define OFF_SRED (4 * TILE_BUF)
#define AS2_BYTES (2 * 16 * 66 * 8)
#define SMEM_BYTES (4 * TILE_BUF + 2048 + 1024)

// ---------------- grid barrier ----------------
__device__ __forceinline__ void grid_sync(unsigned& gen) {
    __syncthreads();
    if (threadIdx.x == 0) {
        __threadfence();
        if (atomicAdd(&g_bar_count, 1u) == (unsigned)(NBLK - 1)) {
            g_bar_count = 0u;
            __threadfence();
            g_bar_gen = gen + 1u;
        } else {
            while (g_bar_gen == gen) { }
        }
        __threadfence();
    }
    __syncthreads();
    ++gen;
}

// named barrier per warp-group (threads 0-255 -> id 1, 256-511 -> id 2)
__device__ __forceinline__ void barw(int wg) {
    asm volatile("bar.sync %0, %1;" :: "r"(wg + 1), "r"(256) : "memory");
}

// ---------------- helpers ----------------
__device__ __forceinline__ uint32_t smem_u32(const void* p) {
    uint32_t a;
    asm("{ .reg .u64 t; cvta.to.shared.u64 t, %1; cvt.u32.u64 %0, t; }" : "=r"(a) : "l"(p));
    return a;
}
__device__ __forceinline__ void ffma2(ull& d, ull a, ull b) {
    asm("fma.rn.f32x2 %0, %1, %2, %0;" : "+l"(d) : "l"(a), "l"(b));
}
__device__ __forceinline__ float4 unpack4(ull p, ull q) {
    float4 o;
    o.x = __uint_as_float((unsigned)p);  o.y = __uint_as_float((unsigned)(p >> 32));
    o.z = __uint_as_float((unsigned)q);  o.w = __uint_as_float((unsigned)(q >> 32));
    return o;
}
__device__ __forceinline__ unsigned pkbf(float a, float b) {
    return (unsigned)__bfloat16_as_ushort(__float2bfloat16(a))
         | ((unsigned)__bfloat16_as_ushort(__float2bfloat16(b)) << 16);
}
__device__ __forceinline__ float bfof(float a) {
    return __bfloat162float(__float2bfloat16(a));
}
__device__ __forceinline__ float act_fn(float h, int id) {
    switch (id) {
        case 0: return fmaxf(h, 0.0f);
        case 1: return 1.0f / (1.0f + expf(-h));
        case 2: return tanhf(h);
        case 3: return (h >= 0.0f) ? h : 0.1f * h;
        default: {
            const float sc = 1.0507009873554804934193349852946f;
            const float al = 1.6732632423543772848170429916717f;
            return (h > 0.0f) ? sc * h : sc * al * expm1f(h);
        }
    }
}

// ---------------- tensor-core / async primitives (baseline PTX) ----------------
__device__ __forceinline__ void ldsm4(uint32_t* r, uint32_t addr) {
    asm volatile("ldmatrix.sync.aligned.m8n8.x4.shared.b16 {%0,%1,%2,%3}, [%4];"
                 : "=r"(r[0]), "=r"(r[1]), "=r"(r[2]), "=r"(r[3]) : "r"(addr));
}
__device__ __forceinline__ void mma16816(float* c, const uint32_t* a, const uint32_t* b) {
    asm volatile(
        "mma.sync.aligned.m16n8k16.row.col.f32.bf16.bf16.f32 "
        "{%0,%1,%2,%3}, {%4,%5,%6,%7}, {%8,%9}, {%0,%1,%2,%3};"
        : "+f"(c[0]), "+f"(c[1]), "+f"(c[2]), "+f"(c[3])
        : "r"(a[0]), "r"(a[1]), "r"(a[2]), "r"(a[3]), "r"(b[0]), "r"(b[1]));
}
__device__ __forceinline__ void cpa16(uint32_t dst, const void* src) {
    asm volatile("cp.async.cg.shared.global [%0], [%1], 16;" :: "r"(dst), "l"(src));
}
__device__ __forceinline__ void cpa_commit() {
    asm volatile("cp.async.commit_group;" ::: "memory");
}
template <int N>
__device__ __forceinline__ void cpa_wait() {
    asm volatile("cp.async.wait_group %0;" :: "n"(N) : "memory");
}
// 128B rows, 16B granules: col16 ^= row&7
__device__ __forceinline__ uint32_t swz(int row, int c16) {
    return (uint32_t)(((row << 3) + (c16 ^ (row & 7))) << 4);
}

// ================= per-warpgroup MMA pipeline (64m x 128n, chunks of K=64) ======
// 256 threads stage one 48KB chunk: 12 cp.async.cg each.
__device__ __forceinline__ void stage_wg(
    uint32_t tb, const bf16* __restrict__ AH, const bf16* __restrict__ AL, size_t sA,
    const bf16* __restrict__ WH, const bf16* __restrict__ WL, size_t sW, int c, int lt)
{
#pragma unroll
    for (int r = 0; r < 2; ++r) {            // A: 64 rows x 8 granules, hi+lo
        const int u = lt + (r << 8), row = u >> 3, g = u & 7;
        const uint32_t o = swz(row, g);
        const size_t s = (size_t)row * sA + (c << 6) + (g << 3);
        cpa16(tb + A_HI + o, AH + s);
        cpa16(tb + A_LO + o, AL + s);
    }
#pragma unroll
    for (int r = 0; r < 4; ++r) {            // B: 128 rows x 8 granules, hi+lo
        const int u = lt + (r << 8), row = u >> 3, g = u & 7;
        const uint32_t o = swz(row, g);
        const size_t s = (size_t)row * sW + (c << 6) + (g << 3);
        cpa16(tb + B_HI + o, WH + s);
        cpa16(tb + B_LO + o, WL + s);
    }
}

// warp tile 32m x 32n: 8 ldsm.x4 per k16 step, 24 mma (3-pass hi/lo)
__device__ __forceinline__ void compute32(uint32_t sb, int lane, int wx, int wy,
                                          float acc[2][4][4])
{
    const int arow = lane & 15, acb = lane >> 4;
    const int brow = (lane & 7) + ((lane >> 4) << 3), bcb = (lane >> 3) & 1;
#pragma unroll
    for (int kk = 0; kk < 4; ++kk) {
        uint32_t ah[2][4], al_[2][4];
#pragma unroll
        for (int i = 0; i < 2; ++i) {
            const int row = wy * 32 + i * 16 + arow;
            const uint32_t o = swz(row, kk * 2 + acb);
            ldsm4(ah[i],  sb + A_HI + o);
            ldsm4(al_[i], sb + A_LO + o);
        }
#pragma unroll
        for (int j = 0; j < 2; ++j) {
            uint32_t bh[4], bl_[4];
            const int row = wx * 32 + j * 16 + brow;
            const uint32_t o = swz(row, kk * 2 + bcb);
            ldsm4(bh,  sb + B_HI + o);
            ldsm4(bl_, sb + B_LO + o);
#pragma unroll
            for (int i = 0; i < 2; ++i)
#pragma unroll
                for (int h = 0; h < 2; ++h) {
                    mma16816(acc[i][j * 2 + h], ah[i],  &bh[h * 2]);
                    mma16816(acc[i][j * 2 + h], ah[i],  &bl_[h * 2]);
                    mma16816(acc[i][j * 2 + h], al_[i], &bh[h * 2]);
                }
        }
    }
}

// independent per-wg pipeline: 2 bufs, named barriers, own cp.async groups
__device__ __forceinline__ void mainloop_wg(
    const bf16* __restrict__ AH, const bf16* __restrict__ AL, size_t sA,
    const bf16* __restrict__ WH, const bf16* __restrict__ WL, size_t sW, int nch,
    uint32_t tu0, int wg, int lt, int lane, int wx, int wy, float acc[2][4][4])
{
    const uint32_t b0 = tu0 + (wg * 2 + 0) * TILE_BUF;
    const uint32_t b1 = tu0 + (wg * 2 + 1) * TILE_BUF;
    stage_wg(b0, AH, AL, sA, WH, WL, sW, 0, lt); cpa_commit();
    stage_wg(b1, AH, AL, sA, WH, WL, sW, 1, lt); cpa_commit();
    for (int c = 0; c < nch; ++c) {
        if (c < nch - 1) cpa_wait<1>(); else cpa_wait<0>();
        barw(wg);                                   // chunk c visible to wg
        const uint32_t sb = (c & 1) ? b1 : b0;
        compute32(sb, lane, wx, wy, acc);
        barw(wg);                                   // wg done reading buf
        if (c + 2 < nch) {
            stage_wg(sb, AH, AL, sA, WH, WL, sW, c + 2, lt);
            cpa_commit();
        }
    }
}

// ================= hidden-layer GEMM: one unit per wg (256 units) ===============
__device__ __forceinline__ void gemm_hidden_tc(
    const bf16* __restrict__ A1H, const bf16* __restrict__ A1L,
    const bf16* __restrict__ A2H, const bf16* __restrict__ A2L,
    const bf16* __restrict__ WHl, const bf16* __restrict__ WLl,
    uint32_t tu0)
{
    const int wg = threadIdx.x >> 8, lt = threadIdx.x & 255;
    const int lane = threadIdx.x & 31, widx = (threadIdx.x >> 5) & 7;
    const int wx = widx & 3, wy = widx >> 2;
    const int uid   = blockIdx.x * 2 + wg;   // 0..255
    const int ntile = uid >> 4;              // 0..15 (128 n)
    const int ks    = uid & 15;              // 0..15 (K=256)
    const int n0    = ntile << 7;
    const int kbeg  = ks << 8;

    const bf16 *AH, *AL;
    if (kbeg < XX) { AH = A1H + kbeg;        AL = A1L + kbeg; }
    else           { AH = A2H + (kbeg - XX); AL = A2L + (kbeg - XX); }
    const bf16* WH = WHl + (size_t)n0 * (2 * XX) + kbeg;
    const bf16* WL = WLl + (size_t)n0 * (2 * XX) + kbeg;

    float acc[2][4][4];
#pragma unroll
    for (int i = 0; i < 2; ++i)
#pragma unroll
        for (int j = 0; j < 4; ++j)
#pragma unroll
            for (int e = 0; e < 4; ++e) acc[i][j][e] = 0.0f;

    mainloop_wg(AH, AL, XX, WH, WL, 2 * XX, 4, tu0, wg, lt, lane, wx, wy, acc);

    float* dst = g_part + (size_t)ks * BBXX + n0;
#pragma unroll
    for (int i = 0; i < 2; ++i) {
        const int row = wy * 32 + i * 16 + (lane >> 2);
#pragma unroll
        for (int j = 0; j < 4; ++j) {
            const int col = wx * 32 + j * 8 + (lane & 3) * 2;
            *(float2*)(dst + (size_t)row * XX + col)       = make_float2(acc[i][j][0], acc[i][j][1]);
            *(float2*)(dst + (size_t)(row + 8) * XX + col) = make_float2(acc[i][j][2], acc[i][j][3]);
        }
    }
}

// ================= pre-pass: h0 jobs, one per wg =================
__device__ __forceinline__ void prepass_tc(
    const float* __restrict__ bin, const int* __restrict__ ids0, uint32_t tu0)
{
    const int wg = threadIdx.x >> 8, lt = threadIdx.x & 255;
    const int lane = threadIdx.x & 31, widx = (threadIdx.x >> 5) & 7;
    const int wx = widx & 3, wy = widx >> 2;

    for (int ju = blockIdx.x * 2 + wg; ju < TT * 16; ju += NBLK * 2) {
        const int t  = ju >> 4;
        const int n0 = (ju & 15) << 7;

        float acc[2][4][4];
#pragma unroll
        for (int i = 0; i < 2; ++i)
#pragma unroll
            for (int j = 0; j < 4; ++j)
#pragma unroll
                for (int e = 0; e < 4; ++e) acc[i][j][e] = 0.0f;

        mainloop_wg(g_xH + (size_t)t * INF, g_xL + (size_t)t * INF, (size_t)TT * INF,
                    g_WiH + (size_t)n0 * INF, g_WiL + (size_t)n0 * INF, INF,
                    8, tu0, wg, lt, lane, wx, wy, acc);

#pragma unroll
        for (int i = 0; i < 2; ++i) {
            const int r0 = wy * 32 + i * 16 + (lane >> 2);
#pragma unroll
            for (int j = 0; j < 4; ++j) {
                const int c0 = n0 + wx * 32 + j * 8 + ((lane & 3) << 1);
                const float2 bb = *(const float2*)(bin + c0);
                const int2  ii = *(const int2*)(ids0 + c0);
                const float vx = act_fn(acc[i][j][0] + bb.x, ii.x);
                const float vy = act_fn(acc[i][j][1] + bb.y, ii.y);
                const float vz = act_fn(acc[i][j][2] + bb.x, ii.x);
                const float vw = act_fn(acc[i][j][3] + bb.y, ii.y);
                const size_t o0 = (size_t)t * BBXX + (size_t)r0 * XX + c0;
                const size_t o1 = o0 + (size_t)8 * XX;
                *(unsigned*)(g_h0H + o0) = pkbf(vx, vy);
                *(unsigned*)(g_h0L + o0) = pkbf(vx - bfof(vx), vy - bfof(vy));
                *(unsigned*)(g_h0H + o1) = pkbf(vz, vw);
                *(unsigned*)(g_h0L + o1) = pkbf(vz - bfof(vz), vw - bfof(vw));
            }
        }
    }
}

// ---------- reduce: 16 slices (A1: 0-7, A2: 8-15 * sc_b) + bias + act + split ----
__device__ __forceinline__ void reduce16(
    const float* __restrict__ bias, const int* __restrict__ ids,
    float* __restrict__ dstF, bf16* __restrict__ dstH, bf16* __restrict__ dstL,
    const float* __restrict__ ss_sc, float* ss_out, float* ss_zero, float* sred)
{
    const int gid = blockIdx.x * NTHR + threadIdx.x;   // 0..65535 (= BBXX/2)
    if (ss_zero != nullptr && gid < BB) ss_zero[gid] = 0.0f;
    const int b = gid >> 10;
    const int n = (gid & 1023) << 1;
    const float* p = g_part + ((size_t)gid << 1);
    float s1x = 0.f, s1y = 0.f, s2x = 0.f, s2y = 0.f;
#pragma unroll
    for (int si = 0; si < 8; ++si) {
        float2 v = __ldcg((const float2*)(p + (size_t)si * BBXX));
        s1x += v.x; s1y += v.y;
    }
#pragma unroll
    for (int si = 8; si < 16; ++si) {
        float2 v = __ldcg((const float2*)(p + (size_t)si * BBXX));
        s2x += v.x; s2y += v.y;
    }
    float sc = 1.0f;
    if (ss_sc != nullptr) {
        float v = __ldcg(ss_sc + b);
        sc = 1.0f / fmaxf(sqrtf(v), 1e-12f);
    }
    const float2 b2 = *(const float2*)(bias + n);
    const int2  id2 = *(const int2*)(ids + n);
    const float ox = act_fn(s1x + sc * s2x + b2.x, id2.x);
    const float oy = act_fn(s1y + sc * s2y + b2.y, id2.y);
    if (dstF != nullptr) *(float2*)(dstF + ((size_t)gid << 1)) = make_float2(ox, oy);
    *(unsigned*)(dstH + ((size_t)gid << 1)) = pkbf(ox, oy);
    const float hx = bfof(ox), hy = bfof(oy);
    *(unsigned*)(dstL + ((size_t)gid << 1)) = pkbf(ox - hx, oy - hy);

    if (ss_out != nullptr) {
        float q = ox * ox + oy * oy;
#pragma unroll
        for (int d = 16; d > 0; d >>= 1) q += __shfl_xor_sync(0xffffffffu, q, d);
        if ((threadIdx.x & 31) == 0) sred[threadIdx.x >> 5] = q;
        __syncthreads();
        if (threadIdx.x == 0) {
            float tot = 0.0f;
#pragma unroll
            for (int w = 0; w < NTHR / 32; ++w) tot += sred[w];
            atomicAdd(ss_out + (blockIdx.x >> 1), tot);   // 2 commutative adds/row
        }
    }
}

// ---------------- hi/lo split of an fp32 array (grid-wide) ----------------
__device__ __forceinline__ void split_arr(const float* __restrict__ src,
                                          bf16* __restrict__ H, bf16* __restrict__ L,
                                          size_t n)
{
    for (size_t i = ((size_t)blockIdx.x * NTHR + threadIdx.x) * 4; i < n;
         i += (size_t)NBLK * NTHR * 4) {
        float4 v = __ldcg((const float4*)(src + i));
        float hx = bfof(v.x), hy = bfof(v.y), hz = bfof(v.z), hw = bfof(v.w);
        *(uint2*)((char*)H + 2 * i) = make_uint2(pkbf(v.x, v.y), pkbf(v.z, v.w));
        *(uint2*)((char*)L + 2 * i) = make_uint2(pkbf(v.x - hx, v.y - hy),
                                                 pkbf(v.z - hz, v.w - hw));
    }
}

// ================= SIMT post pass (512 threads, 4b x 8n thread tile) =======
__device__ __forceinline__ void gemm_core512(
    const float* __restrict__ A, int lda,
    const float* __restrict__ W, int ldw, int nchunks,
    float2* __restrict__ As2, float* __restrict__ Wss, ull acc[4][4])
{
    const int tid = threadIdx.x;
    const int tx = tid & 31, ty = tid >> 5;
    const int lrow = tid >> 2, lk = (tid & 3) << 2;
    const int wrow = tid >> 2, wk = (tid & 3) << 2;
    const bool aload = (tid < 256);

    const float* Ag  = A + (size_t)lrow * lda + lk;
    const float* Wg0 = W + (size_t)wrow * ldw + wk;
    const float* Wg1 = Wg0 + (size_t)128 * ldw;

#pragma unroll
    for (int i = 0; i < 4; ++i)
#pragma unroll
        for (int j = 0; j < 4; ++j) acc[i][j] = 0ull;

    {
        if (aload) {
            float4 av = __ldcg((const float4*)Ag);
            As2[(lk + 0) * 66 + lrow] = make_float2(av.x, av.x);
            As2[(lk + 1) * 66 + lrow] = make_float2(av.y, av.y);
            As2[(lk + 2) * 66 + lrow] = make_float2(av.z, av.z);
            As2[(lk + 3) * 66 + lrow] = make_float2(av.w, av.w);
        }
        float4 w0 = __ldcg((const float4*)Wg0), w1 = __ldcg((const float4*)Wg1);
        Wss[(wk + 0) * 260 + wrow] = w0.x; Wss[(wk + 1) * 260 + wrow] = w0.y;
        Wss[(wk + 2) * 260 + wrow] = w0.z; Wss[(wk + 3) * 260 + wrow] = w0.w;
        Wss[(wk + 0) * 260 + wrow + 128] = w1.x; Wss[(wk + 1) * 260 + wrow + 128] = w1.y;
        Wss[(wk + 2) * 260 + wrow + 128] = w1.z; Wss[(wk + 3) * 260 + wrow + 128] = w1.w;
    }
    __syncthreads();

    for (int c = 0; c < nchunks; ++c) {
        float4 av, w0v, w1v;
        const bool more = (c + 1 < nchunks);
        if (more) {
            if (aload) av = __ldcg((const float4*)(Ag + (c + 1) * KC));
            w0v = __ldcg((const float4*)(Wg0 + (c + 1) * KC));
            w1v = __ldcg((const float4*)(Wg1 + (c + 1) * KC));
        }
        const float2* Ab = As2 + (c & 1) * (16 * 66);
        const float*  Wb = Wss + (c & 1) * (16 * 260);
#pragma unroll
        for (int k = 0; k < KC; ++k) {
            const float2* Ak = Ab + k * 66 + (ty << 2);
            ulonglong2 a01 = *(const ulonglong2*)(Ak);
            ulonglong2 a23 = *(const ulonglong2*)(Ak + 2);
            const float* Wk = Wb + k * 260 + (tx << 2);
            ulonglong2 w0 = *(const ulonglong2*)(Wk);
            ulonglong2 w1 = *(const ulonglong2*)(Wk + 128);
            ffma2(acc[0][0], a01.x, w0.x); ffma2(acc[0][1], a01.x, w0.y);
            ffma2(acc[0][2], a01.x, w1.x); ffma2(acc[0][3], a01.x, w1.y);
            ffma2(acc[1][0], a01.y, w0.x); ffma2(acc[1][1], a01.y, w0.y);
            ffma2(acc[1][2], a01.y, w1.x); ffma2(acc[1][3], a01.y, w1.y);
            ffma2(acc[2][0], a23.x, w0.x); ffma2(acc[2][1], a23.x, w0.y);
            ffma2(acc[2][2], a23.x, w1.x); ffma2(acc[2][3], a23.x, w1.y);
            ffma2(acc[3][0], a23.y, w0.x); ffma2(acc[3][1], a23.y, w0.y);
            ffma2(acc[3][2], a23.y, w1.x); ffma2(acc[3][3], a23.y, w1.y);
        }
        if (more) {
            float2* Abn = As2 + ((c + 1) & 1) * (16 * 66);
            float*  Wbn = Wss + ((c + 1) & 1) * (16 * 260);
            if (aload) {
                Abn[(lk + 0) * 66 + lrow] = make_float2(av.x, av.x);
                Abn[(lk + 1) * 66 + lrow] = make_float2(av.y, av.y);
                Abn[(lk + 2) * 66 + lrow] = make_float2(av.z, av.z);
                Abn[(lk + 3) * 66 + lrow] = make_float2(av.w, av.w);
            }
            Wbn[(wk + 0) * 260 + wrow] = w0v.x; Wbn[(wk + 1) * 260 + wrow] = w0v.y;
            Wbn[(wk + 2) * 260 + wrow] = w0v.z; Wbn[(wk + 3) * 260 + wrow] = w0v.w;
            Wbn[(wk + 0) * 260 + wrow + 128] = w1v.x; Wbn[(wk + 1) * 260 + wrow + 128] = w1v.y;
            Wbn[(wk + 2) * 260 + wrow + 128] = w1v.z; Wbn[(wk + 3) * 260 + wrow + 128] = w1v.w;
            __syncthreads();
        }
    }
}

__device__ __forceinline__ void postpass(const float* __restrict__ Wout,
                                         const float* __restrict__ bout,
                                         const int* __restrict__ oids,
                                         float* __restrict__ out,
                                         float2* As2, float* Wss)
{
    for (int t = blockIdx.x; t < TT; t += NBLK) {
        ull acc[4][4];
        gemm_core512(g_h4all + (size_t)t * BBXX, XX, Wout, XX, XX / KC, As2, Wss, acc);
        const int tx = threadIdx.x & 31, ty = threadIdx.x >> 5;
        const int c0 = tx << 2;
        float4 b0 = *(const float4*)(bout + c0), b1 = *(const float4*)(bout + c0 + 128);
        int4 i0 = *(const int4*)(oids + c0), i1 = *(const int4*)(oids + c0 + 128);
#pragma unroll
        for (int r = 0; r < 4; ++r) {
            const int b = (ty << 2) + r;
            float* dst = out + (size_t)b * (TT * OUTF) + (size_t)t * OUTF + c0;
            float4 v0 = unpack4(acc[r][0], acc[r][1]);
            float4 v1 = unpack4(acc[r][2], acc[r][3]);
            v0.x = act_fn(v0.x + b0.x, i0.x); v0.y = act_fn(v0.y + b0.y, i0.y);
            v0.z = act_fn(v0.z + b0.z, i0.z); v0.w = act_fn(v0.w + b0.w, i0.w);
            v1.x = act_fn(v1.x + b1.x, i1.x); v1.y = act_fn(v1.y + b1.y, i1.y);
            v1.z = act_fn(v1.z + b1.z, i1.z); v1.w = act_fn(v1.w + b1.w, i1.w);
            *(float4*)dst = v0; *(float4*)(dst + 128) = v1;
        }
    }
}

// ---------------- persistent mega-kernel ----------------
__global__ void __launch_bounds__(NTHR, 1)
bnn_kernel(const float* __restrict__ x,     const float* __restrict__ Win,
           const float* __restrict__ bin,   const float* __restrict__ Wh,
           const float* __restrict__ bh,    const float* __restrict__ Wout,
           const float* __restrict__ bout,  const int* __restrict__ act_ids,
           const int* __restrict__ out_ids, float* __restrict__ out)
{
    extern __shared__ char smraw[];
    const uint32_t sbase = smem_u32(smraw);
    const uint32_t tu0 = (sbase + 1023u) & ~1023u;
    char* tiles = smraw + (tu0 - sbase);
    float* sred = (float*)(tiles + OFF_SRED);
    float2* As2 = (float2*)tiles;
    float*  Wss = (float*)(tiles + AS2_BYTES);

    unsigned gen = g_bar_gen;

    // fresh state each launch
    if (blockIdx.x == 0 && threadIdx.x < 256) {
        if (threadIdx.x < 128) ((float*)g_liss)[threadIdx.x] = 0.0f;
        else                   ((float*)g_bpss)[threadIdx.x - 128] = 0.0f;
    }
    for (int i = blockIdx.x * NTHR + threadIdx.x; i < BBXX; i += NBLK * NTHR) {
        g_h4H[i] = __ushort_as_bfloat16(0); g_h4L[i] = __ushort_as_bfloat16(0);
        g_h2H[1][i] = __ushort_as_bfloat16(0); g_h2L[1][i] = __ushort_as_bfloat16(0);
    }
    split_arr(Wh, g_WhH, g_WhL, 4ull * XX * 2 * XX);
    split_arr(Win, g_WiH, g_WiL, (size_t)XX * INF);
    split_arr(x, g_xH, g_xL, (size_t)BB * TT * INF);
    grid_sync(gen);

    prepass_tc(bin, act_ids, tu0);
    grid_sync(gen);

    const size_t WH = (size_t)XX * 2 * XX;
    for (int t = 0; t < TT; ++t) {
        const int p = t & 1, q = p ^ 1;
        const size_t toff = (size_t)t * BBXX;
        const size_t poff = (t > 0) ? (toff - BBXX) : 0;

        // h1 = act([h0 | bp] Wh0^T + bh0),  bp-scale applied in reduce
        gemm_hidden_tc(g_h0H + toff, g_h0L + toff, g_h4H + poff, g_h4L + poff,
                       g_WhH, g_WhL, tu0);
        grid_sync(gen);
        reduce16(bh, act_ids + XX, nullptr, g_h1H, g_h1L,
                 (const float*)g_bpss[q], nullptr, nullptr, sred);
        grid_sync(gen);

        // h2 = act([h1 | li] Wh1^T + bh1)
        gemm_hidden_tc(g_h1H, g_h1L, g_h2H[q], g_h2L[q],
                       g_WhH + WH, g_WhL + WH, tu0);
        grid_sync(gen);
        reduce16(bh + XX, act_ids + 2 * XX, nullptr, g_h2H[p], g_h2L[p],
                 (const float*)g_liss[q], (float*)g_liss[p], (float*)g_bpss[q], sred);
        grid_sync(gen);

        // h3 = act([h2 | h1] Wh2^T + bh2)
        gemm_hidden_tc(g_h2H[p], g_h2L[p], g_h1H, g_h1L,
                       g_WhH + 2 * WH, g_WhL + 2 * WH, tu0);
        grid_sync(gen);
        reduce16(bh + 2 * XX, act_ids + 3 * XX, nullptr, g_h3H, g_h3L,
                 nullptr, nullptr, (float*)g_liss[q], sred);
        grid_sync(gen);

        // h4 = act([h3 | h2] Wh3^T + bh3)
        gemm_hidden_tc(g_h3H, g_h3L, g_h2H[p], g_h2L[p],
                       g_WhH + 3 * WH, g_WhL + 3 * WH, tu0);
        grid_sync(gen);
        reduce16(bh + 3 * XX, act_ids + 4 * XX, g_h4all + toff,
                 g_h4H + toff, g_h4L + toff,
                 nullptr, (float*)g_bpss[p], nullptr, sred);
        grid_sync(gen);
    }

    postpass(Wout, bout, out_ids, out, As2, Wss);
}

extern "C" void kernel_launch(void* const* d_in, const int* in_sizes, int n_in,
                              void* d_out, int out_size)
{
    (void)in_sizes; (void)n_in; (void)out_size;
    const float* x       = (const float*)d_in[0];
    const float* W_in    = (const float*)d_in[1];
    const float* b_in    = (const float*)d_in[2];
    const float* W_h     = (const float*)d_in[3];
    const float* b_h     = (const float*)d_in[4];
    const float* W_out   = (const float*)d_in[5];
    const float* b_out   = (const float*)d_in[6];
    const int*   act_ids = (const int*)d_in[7];
    const int*   out_ids = (const int*)d_in[8];
    float*       out     = (float*)d_out;

    cudaFuncSetAttribute(bnn_kernel, cudaFuncAttributeMaxDynamicSharedMemorySize,
                         SMEM_BYTES);
    bnn_kernel<<<NBLK, NTHR, SMEM_BYTES>>>(x, W_in, b_in, W_h, b_h, W_out, b_out,
                                           act_ids, out_ids, out);
}